// round 1
// baseline (speedup 1.0000x reference)
#include <cuda_runtime.h>

#define BSZ 512
#define VV  30000
#define K0  128
#define EPSF 2.2e-10f
#define MBR 100.0f

// ---------------- scratch (device globals: allocation-free) ----------------
__device__ float g_xT[VV * BSZ];      // x transposed (V,B)
__device__ float g_ratio[VV * BSZ];   // ratio (D,B), reused per layer
__device__ float g_W[VV * K0];        // WSZS / step / p, reused
__device__ float g_acc[K0 * BSZ];     // phi^T @ ratio accumulator
__device__ float g_xa[K0 * BSZ];      // x_cur after layer 0
__device__ float g_xb[K0 * BSZ];      // x_cur after layer 1
__device__ float g_S[K0];
__device__ float g_T[K0];
__device__ float g_P[K0];

// ---------------- digamma ----------------
__device__ __forceinline__ float digammaf_(float x) {
    float r = 0.f;
    while (x < 6.f) { r -= 1.f / x; x += 1.f; }
    float inv  = 1.f / x;
    float inv2 = inv * inv;
    float ser  = inv2 * (0.08333333333f - inv2 * (0.008333333333f - inv2 * 0.003968253968f));
    return r + logf(x) - 0.5f * inv - ser;
}

// ---------------- zero accumulators ----------------
__global__ void zero_kernel(float* S, float* T, float* P, int K, float* acc, int accN) {
    int i = blockIdx.x * blockDim.x + threadIdx.x;
    if (i < K) { S[i] = 0.f; T[i] = 0.f; P[i] = 0.f; }
    if (i < accN) acc[i] = 0.f;
}

// ---------------- transpose x (B,V) -> (V,B) ----------------
__global__ void transpose_kernel(const float* __restrict__ x, float* __restrict__ xT) {
    __shared__ float tile[32][33];
    int v0 = blockIdx.x * 32, b0 = blockIdx.y * 32;
    int tx = threadIdx.x, ty = threadIdx.y;   // 32 x 8
#pragma unroll
    for (int i = 0; i < 32; i += 8) {
        int b = b0 + ty + i, v = v0 + tx;
        tile[ty + i][tx] = (v < VV) ? x[b * VV + v] : 0.f;
    }
    __syncthreads();
#pragma unroll
    for (int i = 0; i < 32; i += 8) {
        int v = v0 + ty + i, b = b0 + tx;
        if (v < VV) xT[v * BSZ + b] = tile[tx][ty + i];
    }
}

// ---------------- GEMM1: denom = phi@theta ; ratio = f(xcur, denom) ----------------
// phi: (D,K), theta: (K,512), xcur: (D,512), ratio: (D,512)
__global__ void ratio_gemm(int D, int K,
                           const float* __restrict__ phi,
                           const float* __restrict__ theta,
                           const float* __restrict__ xcur,
                           int mode,  // 0: x/denom, 1: digamma(denom+x)-digamma(denom)
                           float* __restrict__ ratio) {
    __shared__ float As[16][65];  // [k][v]
    __shared__ float Bs[16][65];  // [k][b]
    const int bb = blockIdx.x * 64;
    const int bv = blockIdx.y * 64;
    const int tid = threadIdx.x;
    const int tx = tid & 15, ty = tid >> 4;
    float acc[4][4] = {};

    for (int kk = 0; kk < K; kk += 16) {
#pragma unroll
        for (int e = 0; e < 4; e++) {
            int idx = tid + e * 256;           // 1024 elems
            int r = idx >> 4, c = idx & 15;    // r: v-offset, c: k-offset
            int v = bv + r;
            As[c][r] = (v < D) ? phi[v * K + kk + c] : 0.f;
        }
#pragma unroll
        for (int e = 0; e < 4; e++) {
            int idx = tid + e * 256;
            int r = idx >> 6, c = idx & 63;    // r: k-offset, c: b-offset
            Bs[r][c] = theta[(kk + r) * BSZ + bb + c];
        }
        __syncthreads();
#pragma unroll
        for (int kc = 0; kc < 16; kc++) {
            float a[4], b[4];
            a[0] = As[kc][ty]; a[1] = As[kc][ty + 16]; a[2] = As[kc][ty + 32]; a[3] = As[kc][ty + 48];
            b[0] = Bs[kc][tx]; b[1] = Bs[kc][tx + 16]; b[2] = Bs[kc][tx + 32]; b[3] = Bs[kc][tx + 48];
#pragma unroll
            for (int i = 0; i < 4; i++)
#pragma unroll
                for (int j = 0; j < 4; j++) acc[i][j] += a[i] * b[j];
        }
        __syncthreads();
    }
#pragma unroll
    for (int i = 0; i < 4; i++) {
        int v = bv + ty + i * 16;
        if (v >= D) continue;
#pragma unroll
        for (int j = 0; j < 4; j++) {
            int b = bb + tx + j * 16;
            float denom = fmaxf(acc[i][j], EPSF);
            float xv = xcur[v * BSZ + b];
            float r;
            if (mode == 0) r = xv / denom;
            else           r = digammaf_(denom + xv) - digammaf_(denom);
            ratio[v * BSZ + b] = r;
        }
    }
}

// ---------------- GEMM2: W = phi * (ratio @ theta^T) ----------------
// ratio: (D,512), theta: (K,512), phi,W: (D,K)
__global__ void wszs_gemm(int D, int K,
                          const float* __restrict__ ratio,
                          const float* __restrict__ theta,
                          const float* __restrict__ phi,
                          float* __restrict__ W) {
    __shared__ float Rs[16][65];  // [b][v]
    __shared__ float Ts[16][65];  // [b][k]
    const int bk = blockIdx.x * 64;
    const int bv = blockIdx.y * 64;
    const int tid = threadIdx.x;
    const int tx = tid & 15, ty = tid >> 4;   // tx -> k, ty -> v
    float acc[4][4] = {};

    for (int bbk = 0; bbk < BSZ; bbk += 16) {
#pragma unroll
        for (int e = 0; e < 4; e++) {
            int idx = tid + e * 256;
            int r = idx >> 4, c = idx & 15;
            int v = bv + r;
            Rs[c][r] = (v < D) ? ratio[v * BSZ + bbk + c] : 0.f;
        }
#pragma unroll
        for (int e = 0; e < 4; e++) {
            int idx = tid + e * 256;
            int r = idx >> 4, c = idx & 15;
            int k = bk + r;
            Ts[c][r] = (k < K) ? theta[k * BSZ + bbk + c] : 0.f;
        }
        __syncthreads();
#pragma unroll
        for (int bc = 0; bc < 16; bc++) {
            float a[4], b[4];
            a[0] = Rs[bc][ty]; a[1] = Rs[bc][ty + 16]; a[2] = Rs[bc][ty + 32]; a[3] = Rs[bc][ty + 48];
            b[0] = Ts[bc][tx]; b[1] = Ts[bc][tx + 16]; b[2] = Ts[bc][tx + 32]; b[3] = Ts[bc][tx + 48];
#pragma unroll
            for (int i = 0; i < 4; i++)
#pragma unroll
                for (int j = 0; j < 4; j++) acc[i][j] += a[i] * b[j];
        }
        __syncthreads();
    }
#pragma unroll
    for (int i = 0; i < 4; i++) {
        int v = bv + ty + i * 16;
        if (v >= D) continue;
#pragma unroll
        for (int j = 0; j < 4; j++) {
            int k = bk + tx + j * 16;
            if (k < K) W[v * K + k] = phi[v * K + k] * acc[i][j];
        }
    }
}

// ---------------- column sum of W -> S ----------------
__global__ void colsum_kernel(int D, int K, const float* __restrict__ W, float* __restrict__ S) {
    int k = threadIdx.x;
    int v0 = blockIdx.x * 64;
    float s = 0.f;
    for (int r = 0; r < 64; r++) {
        int v = v0 + r;
        if (v < D) s += W[v * K + k];
    }
    atomicAdd(&S[k], s);
}

// ---------------- TLASGR step: W <- step ; T[k] += colsum(step) ----------------
__global__ void step_kernel(int D, int K,
                            const float* __restrict__ phi,
                            const float* __restrict__ noise,
                            const float* __restrict__ S,
                            float* __restrict__ W,
                            float* __restrict__ T) {
    int k = threadIdx.x;
    int v0 = blockIdx.x * 64;
    float s = S[k];
    float ndot = MBR * s;
    float inv_n = 1.f / fmaxf(ndot, EPSF);
    float tmpsum = MBR * s + 0.1f * (float)D;
    float c2 = sqrtf(2.f * inv_n);
    float tsum = 0.f;
    for (int r = 0; r < 64; r++) {
        int v = v0 + r;
        if (v < D) {
            int idx = v * K + k;
            float w = W[idx], ph = phi[idx], nz = noise[idx];
            float tmp = MBR * w + 0.1f;
            float st = ph + inv_n * (tmp - tmpsum * ph) + c2 * sqrtf(ph) * nz;
            W[idx] = st;
            tsum += st;
        }
    }
    atomicAdd(&T[k], tsum);
}

// ---------------- simplex projection part 1: W <- p ; P[k] += colsum(p) ----------------
__global__ void p_kernel(int D, int K,
                         const float* __restrict__ phi,
                         float* __restrict__ W,
                         const float* __restrict__ T,
                         float* __restrict__ P) {
    int k = threadIdx.x;
    int v0 = blockIdx.x * 64;
    float a = T[k] - 1.f;
    float psum = 0.f;
    for (int r = 0; r < 64; r++) {
        int v = v0 + r;
        if (v < D) {
            int idx = v * K + k;
            float p = fmaxf(EPSF, W[idx] - a * phi[idx]);
            W[idx] = p;
            psum += p;
        }
    }
    atomicAdd(&P[k], psum);
}

// ---------------- normalize: out = p / max(EPS, colsum(p)) ----------------
__global__ void norm_kernel(int D, int K,
                            const float* __restrict__ W,
                            const float* __restrict__ P,
                            float* __restrict__ out) {
    int k = threadIdx.x;
    int v0 = blockIdx.x * 64;
    float inv = 1.f / fmaxf(EPSF, P[k]);
    for (int r = 0; r < 64; r++) {
        int v = v0 + r;
        if (v < D) out[v * K + k] = W[v * K + k] * inv;
    }
}

// ---------------- GEMM3 (split-K): acc(K,512) += phi^T @ ratio ----------------
__global__ void xnext_gemm(int D, int K, int chunk,
                           const float* __restrict__ phi,
                           const float* __restrict__ ratio,
                           float* __restrict__ acc) {
    __shared__ float Ps[16][65];  // [v][k]
    __shared__ float Rs[16][65];  // [v][b]
    const int bk = blockIdx.x * 64;
    const int bb = blockIdx.y * 64;
    const int v0 = blockIdx.z * chunk;
    const int vend = min(v0 + chunk, D);
    const int tid = threadIdx.x;
    const int tx = tid & 15, ty = tid >> 4;   // tx -> b, ty -> k
    float c[4][4] = {};

    for (int vv = v0; vv < vend; vv += 16) {
#pragma unroll
        for (int e = 0; e < 4; e++) {
            int idx = tid + e * 256;
            int r = idx >> 6, col = idx & 63;
            int v = vv + r;
            int k = bk + col;
            Ps[r][col] = (v < vend && k < K) ? phi[v * K + k] : 0.f;
        }
#pragma unroll
        for (int e = 0; e < 4; e++) {
            int idx = tid + e * 256;
            int r = idx >> 6, col = idx & 63;
            int v = vv + r;
            Rs[r][col] = (v < vend) ? ratio[v * BSZ + bb + col] : 0.f;
        }
        __syncthreads();
#pragma unroll
        for (int vc = 0; vc < 16; vc++) {
            float a[4], b[4];
            a[0] = Ps[vc][ty]; a[1] = Ps[vc][ty + 16]; a[2] = Ps[vc][ty + 32]; a[3] = Ps[vc][ty + 48];
            b[0] = Rs[vc][tx]; b[1] = Rs[vc][tx + 16]; b[2] = Rs[vc][tx + 32]; b[3] = Rs[vc][tx + 48];
#pragma unroll
            for (int i = 0; i < 4; i++)
#pragma unroll
                for (int j = 0; j < 4; j++) c[i][j] += a[i] * b[j];
        }
        __syncthreads();
    }
#pragma unroll
    for (int i = 0; i < 4; i++) {
        int k = bk + ty + i * 16;
        if (k >= K) continue;
#pragma unroll
        for (int j = 0; j < 4; j++) {
            int b = bb + tx + j * 16;
            atomicAdd(&acc[k * BSZ + b], c[i][j]);
        }
    }
}

// ---------------- x_cur = theta * acc ----------------
__global__ void xmul_kernel(int K,
                            const float* __restrict__ theta,
                            const float* __restrict__ acc,
                            float* __restrict__ xcur) {
    int i = blockIdx.x * blockDim.x + threadIdx.x;
    if (i < K * BSZ) xcur[i] = theta[i] * acc[i];
}

// ---------------- host orchestration ----------------
static void run_layer(int t, int D, int K,
                      const float* phi, const float* theta, const float* noise,
                      const float* xcur_in, float* ratio, float* W,
                      float* acc, float* xcur_out,
                      float* S, float* T, float* P,
                      float* out_off, bool doNext) {
    int accN = doNext ? K * BSZ : 0;
    int zn = (accN > K) ? accN : K;
    zero_kernel<<<(zn + 255) / 256, 256>>>(S, T, P, K, acc, accN);

    dim3 g1(BSZ / 64, (D + 63) / 64);
    ratio_gemm<<<g1, 256>>>(D, K, phi, theta, xcur_in, (t == 0) ? 0 : 1, ratio);

    dim3 g2((K + 63) / 64, (D + 63) / 64);
    wszs_gemm<<<g2, 256>>>(D, K, ratio, theta, phi, W);

    int gcol = (D + 63) / 64;
    colsum_kernel<<<gcol, K>>>(D, K, W, S);
    step_kernel<<<gcol, K>>>(D, K, phi, noise, S, W, T);
    p_kernel<<<gcol, K>>>(D, K, phi, W, T, P);
    norm_kernel<<<gcol, K>>>(D, K, W, P, out_off);

    if (doNext) {
        int chunk = (D > 4096) ? 2048 : D;
        dim3 g3((K + 63) / 64, BSZ / 64, (D + chunk - 1) / chunk);
        xnext_gemm<<<g3, 256>>>(D, K, chunk, phi, ratio, acc);
        xmul_kernel<<<(K * BSZ + 255) / 256, 256>>>(K, theta, acc, xcur_out);
    }
}

extern "C" void kernel_launch(void* const* d_in, const int* in_sizes, int n_in,
                              void* d_out, int out_size) {
    const float* x      = (const float*)d_in[0];
    const float* theta0 = (const float*)d_in[1];
    const float* theta1 = (const float*)d_in[2];
    const float* theta2 = (const float*)d_in[3];
    const float* phi0   = (const float*)d_in[4];
    const float* phi1   = (const float*)d_in[5];
    const float* phi2   = (const float*)d_in[6];
    const float* noise0 = (const float*)d_in[7];
    const float* noise1 = (const float*)d_in[8];
    const float* noise2 = (const float*)d_in[9];
    float* out = (float*)d_out;

    float *xT, *ratio, *W, *acc, *xa, *xb, *S, *T, *P;
    cudaGetSymbolAddress((void**)&xT, g_xT);
    cudaGetSymbolAddress((void**)&ratio, g_ratio);
    cudaGetSymbolAddress((void**)&W, g_W);
    cudaGetSymbolAddress((void**)&acc, g_acc);
    cudaGetSymbolAddress((void**)&xa, g_xa);
    cudaGetSymbolAddress((void**)&xb, g_xb);
    cudaGetSymbolAddress((void**)&S, g_S);
    cudaGetSymbolAddress((void**)&T, g_T);
    cudaGetSymbolAddress((void**)&P, g_P);

    // transpose x -> (V,B)
    dim3 gt((VV + 31) / 32, BSZ / 32);
    transpose_kernel<<<gt, dim3(32, 8)>>>(x, xT);

    // Layer 0: D=30000, K=128
    run_layer(0, VV, 128, phi0, theta0, noise0, xT, ratio, W, acc, xa,
              S, T, P, out, true);
    // Layer 1: D=128, K=64
    run_layer(1, 128, 64, phi1, theta1, noise1, xa, ratio, W, acc, xb,
              S, T, P, out + VV * 128, true);
    // Layer 2: D=64, K=32 (x_cur output unused)
    run_layer(2, 64, 32, phi2, theta2, noise2, xb, ratio, W, acc, nullptr,
              S, T, P, out + VV * 128 + 128 * 64, false);
}

// round 2
// speedup vs baseline: 1.2133x; 1.2133x over previous
#include <cuda_runtime.h>

#define BSZ 512
#define VV  30000
#define K0  128
#define EPSF 2.2e-10f
#define MBR 100.0f
#define NZ0 37          // split-K slices for layer-0 xnext (37*4 = 148 blocks)

// ---------------- scratch (device globals: allocation-free) ----------------
__device__ float g_xT[VV * BSZ];            // x transposed (V,B)
__device__ float g_ratio[VV * BSZ];         // ratio (D,B), reused per layer
__device__ float g_W[VV * K0];              // WSZS / p, reused
__device__ float g_part[NZ0 * K0 * BSZ];    // split-K partials for phi^T@ratio
__device__ float g_xa[K0 * BSZ];
__device__ float g_xb[K0 * BSZ];
__device__ float g_S[K0];
__device__ float g_P[K0];
__device__ float g_phisum[K0];
__device__ float g_qsum[K0];

// ---------------- digamma ----------------
__device__ __forceinline__ float digammaf_(float x) {
    float r = 0.f;
    while (x < 6.f) { r -= 1.f / x; x += 1.f; }
    float inv  = 1.f / x;
    float inv2 = inv * inv;
    float ser  = inv2 * (0.08333333333f - inv2 * (0.008333333333f - inv2 * 0.003968253968f));
    return r + logf(x) - 0.5f * inv - ser;
}

// ---------------- zero small accumulators ----------------
__global__ void zero4_kernel(float* S, float* P, float* A, float* Q, int K) {
    int i = threadIdx.x;
    if (i < K) { S[i] = 0.f; P[i] = 0.f; A[i] = 0.f; Q[i] = 0.f; }
}

// ---------------- transpose x (B,V) -> (V,B) ----------------
__global__ void transpose_kernel(const float* __restrict__ x, float* __restrict__ xT) {
    __shared__ float tile[32][33];
    int v0 = blockIdx.x * 32, b0 = blockIdx.y * 32;
    int tx = threadIdx.x, ty = threadIdx.y;   // 32 x 8
#pragma unroll
    for (int i = 0; i < 32; i += 8) {
        int b = b0 + ty + i, v = v0 + tx;
        tile[ty + i][tx] = (v < VV) ? x[b * VV + v] : 0.f;
    }
    __syncthreads();
#pragma unroll
    for (int i = 0; i < 32; i += 8) {
        int v = v0 + ty + i, b = b0 + tx;
        if (v < VV) xT[v * BSZ + b] = tile[tx][ty + i];
    }
}

// ---------------- colstats: phisum[k]=colsum(phi), qsum[k]=colsum(sqrt(phi)*noise) ----
__global__ void colstats_kernel(int D, int K,
                                const float* __restrict__ phi,
                                const float* __restrict__ noise,
                                float* __restrict__ phisum, float* __restrict__ qsum) {
    __shared__ float sA[128], sB[128];
    int tid = threadIdx.x;
    if (tid < K) { sA[tid] = 0.f; sB[tid] = 0.f; }
    __syncthreads();
    int base = blockIdx.x * 4096;
    int k = (base + tid) & (K - 1);   // K is a power of two; 256 % K == 0
    float pa = 0.f, pb = 0.f;
    int DK = D * K;
#pragma unroll 4
    for (int e = 0; e < 16; e++) {
        int idx = base + e * 256 + tid;
        if (idx < DK) {
            float ph = phi[idx], nz = noise[idx];
            pa += ph;
            pb += sqrtf(ph) * nz;
        }
    }
    atomicAdd(&sA[k], pa);
    atomicAdd(&sB[k], pb);
    __syncthreads();
    if (tid < K) { atomicAdd(&phisum[tid], sA[tid]); atomicAdd(&qsum[tid], sB[tid]); }
}

// ============================================================================
// GEMM kernels: 128x128 block tile, 256 threads, 8x8 microtile, BK=16
// thread (trow=tid/16, tcol=tid%16): rows trow*4+{0..3}, trow*4+64+{0..3}
//                                    cols tcol*4+{0..3}, tcol*4+64+{0..3}
// ============================================================================

// GEMM1: denom = phi@theta (DxK @ Kx512); ratio = f(xcur, denom)
__global__ __launch_bounds__(256, 2) void ratio_gemm_opt(
    int D, int K,
    const float* __restrict__ phi, const float* __restrict__ theta,
    const float* __restrict__ xcur, int mode, float* __restrict__ ratio) {
    __shared__ float As[16][132];   // [k_inner][v]
    __shared__ float Bs[16][132];   // [k_inner][b]
    const int bn = blockIdx.x * 128;   // b
    const int bv = blockIdx.y * 128;   // v
    const int tid = threadIdx.x;
    const int trow = tid >> 4, tcol = tid & 15;
    float acc[8][8] = {};

    for (int kk = 0; kk < K; kk += 16) {
#pragma unroll
        for (int e = 0; e < 8; e++) {           // A transpose-load
            int idx = tid + e * 256;
            int ic = idx & 15, m = idx >> 4;
            As[ic][m] = (bv + m < D) ? phi[(bv + m) * K + kk + ic] : 0.f;
        }
#pragma unroll
        for (int e = 0; e < 2; e++) {           // B direct float4 load
            int idx = tid + e * 256;
            int r = idx >> 5, c4 = idx & 31;
            *(float4*)&Bs[r][c4 * 4] = *(const float4*)&theta[(kk + r) * BSZ + bn + c4 * 4];
        }
        __syncthreads();
#pragma unroll
        for (int kc = 0; kc < 16; kc++) {
            float a[8], b[8];
            *(float4*)&a[0] = *(float4*)&As[kc][trow * 4];
            *(float4*)&a[4] = *(float4*)&As[kc][trow * 4 + 64];
            *(float4*)&b[0] = *(float4*)&Bs[kc][tcol * 4];
            *(float4*)&b[4] = *(float4*)&Bs[kc][tcol * 4 + 64];
#pragma unroll
            for (int i = 0; i < 8; i++)
#pragma unroll
                for (int j = 0; j < 8; j++) acc[i][j] += a[i] * b[j];
        }
        __syncthreads();
    }
#pragma unroll
    for (int i = 0; i < 8; i++) {
        int v = bv + trow * 4 + (i & 3) + ((i >> 2) << 6);
        if (v >= D) continue;
#pragma unroll
        for (int jg = 0; jg < 2; jg++) {
            int b = bn + tcol * 4 + (jg << 6);
            float4 xv = *(const float4*)&xcur[v * BSZ + b];
            float xs[4] = {xv.x, xv.y, xv.z, xv.w};
            float rs[4];
#pragma unroll
            for (int j = 0; j < 4; j++) {
                float d = fmaxf(acc[i][jg * 4 + j], EPSF);
                rs[j] = (mode == 0) ? xs[j] / d
                                    : digammaf_(d + xs[j]) - digammaf_(d);
            }
            float4 r4 = {rs[0], rs[1], rs[2], rs[3]};
            *(float4*)&ratio[v * BSZ + b] = r4;
        }
    }
}

// GEMM2: W[v][k] = phi[v][k] * sum_b ratio[v][b]*theta[k][b]; S[k] += colsum(W)
__global__ __launch_bounds__(256, 2) void wszs_gemm_opt(
    int D, int K,
    const float* __restrict__ ratio, const float* __restrict__ theta,
    const float* __restrict__ phi, float* __restrict__ W, float* __restrict__ S) {
    __shared__ float As[16][132];   // [b_inner][v]
    __shared__ float Bs[16][132];   // [b_inner][k]
    __shared__ float sS[128];
    const int bn = blockIdx.x * 128;   // k
    const int bv = blockIdx.y * 128;   // v
    const int tid = threadIdx.x;
    const int trow = tid >> 4, tcol = tid & 15;
    float acc[8][8] = {};

    for (int kk = 0; kk < BSZ; kk += 16) {
#pragma unroll
        for (int e = 0; e < 8; e++) {
            int idx = tid + e * 256;
            int ic = idx & 15, m = idx >> 4;
            As[ic][m] = (bv + m < D) ? ratio[(bv + m) * BSZ + kk + ic] : 0.f;
        }
#pragma unroll
        for (int e = 0; e < 8; e++) {
            int idx = tid + e * 256;
            int ic = idx & 15, m = idx >> 4;
            Bs[ic][m] = (bn + m < K) ? theta[(bn + m) * BSZ + kk + ic] : 0.f;
        }
        __syncthreads();
#pragma unroll
        for (int kc = 0; kc < 16; kc++) {
            float a[8], b[8];
            *(float4*)&a[0] = *(float4*)&As[kc][trow * 4];
            *(float4*)&a[4] = *(float4*)&As[kc][trow * 4 + 64];
            *(float4*)&b[0] = *(float4*)&Bs[kc][tcol * 4];
            *(float4*)&b[4] = *(float4*)&Bs[kc][tcol * 4 + 64];
#pragma unroll
            for (int i = 0; i < 8; i++)
#pragma unroll
                for (int j = 0; j < 8; j++) acc[i][j] += a[i] * b[j];
        }
        __syncthreads();
    }
    if (tid < 128) sS[tid] = 0.f;
    __syncthreads();
    float colp[8] = {};
#pragma unroll
    for (int i = 0; i < 8; i++) {
        int v = bv + trow * 4 + (i & 3) + ((i >> 2) << 6);
        if (v >= D) continue;
#pragma unroll
        for (int jg = 0; jg < 2; jg++) {
            int k4 = bn + tcol * 4 + (jg << 6);
            if (k4 < K) {
                float4 ph = *(const float4*)&phi[v * K + k4];
                float4 wv;
                wv.x = ph.x * acc[i][jg * 4 + 0];
                wv.y = ph.y * acc[i][jg * 4 + 1];
                wv.z = ph.z * acc[i][jg * 4 + 2];
                wv.w = ph.w * acc[i][jg * 4 + 3];
                *(float4*)&W[v * K + k4] = wv;
                colp[jg * 4 + 0] += wv.x;
                colp[jg * 4 + 1] += wv.y;
                colp[jg * 4 + 2] += wv.z;
                colp[jg * 4 + 3] += wv.w;
            }
        }
    }
#pragma unroll
    for (int j = 0; j < 8; j++)
        atomicAdd(&sS[tcol * 4 + (j & 3) + ((j >> 2) << 6)], colp[j]);
    __syncthreads();
    if (tid < 128 && bn + tid < K) atomicAdd(&S[bn + tid], sS[tid]);
}

// GEMM3 (split-K): part[z][k][b] = sum_{v in chunk z} phi[v][k]*ratio[v][b]
__global__ __launch_bounds__(256, 2) void xnext_gemm_opt(
    int D, int K, int chunk,
    const float* __restrict__ phi, const float* __restrict__ ratio,
    float* __restrict__ part) {
    __shared__ float As[16][132];   // [v_inner][k]
    __shared__ float Bs[16][132];   // [v_inner][b]
    const int bn = blockIdx.x * 128;   // b
    const int z = blockIdx.z;
    const int v0 = z * chunk;
    const int vend = min(v0 + chunk, D);
    const int tid = threadIdx.x;
    const int trow = tid >> 4, tcol = tid & 15;
    float acc[8][8] = {};

    for (int kk = v0; kk < vend; kk += 16) {
#pragma unroll
        for (int e = 0; e < 2; e++) {           // A: phi rows (v) x K cols, direct
            int idx = tid + e * 256;
            int r = idx >> 5, c4 = idx & 31;
            float4 val = {0.f, 0.f, 0.f, 0.f};
            if (kk + r < vend && c4 * 4 < K)
                val = *(const float4*)&phi[(kk + r) * K + c4 * 4];
            *(float4*)&As[r][c4 * 4] = val;
        }
#pragma unroll
        for (int e = 0; e < 2; e++) {           // B: ratio rows (v) x b cols, direct
            int idx = tid + e * 256;
            int r = idx >> 5, c4 = idx & 31;
            float4 val = {0.f, 0.f, 0.f, 0.f};
            if (kk + r < vend)
                val = *(const float4*)&ratio[(kk + r) * BSZ + bn + c4 * 4];
            *(float4*)&Bs[r][c4 * 4] = val;
        }
        __syncthreads();
#pragma unroll
        for (int kc = 0; kc < 16; kc++) {
            float a[8], b[8];
            *(float4*)&a[0] = *(float4*)&As[kc][trow * 4];
            *(float4*)&a[4] = *(float4*)&As[kc][trow * 4 + 64];
            *(float4*)&b[0] = *(float4*)&Bs[kc][tcol * 4];
            *(float4*)&b[4] = *(float4*)&Bs[kc][tcol * 4 + 64];
#pragma unroll
            for (int i = 0; i < 8; i++)
#pragma unroll
                for (int j = 0; j < 8; j++) acc[i][j] += a[i] * b[j];
        }
        __syncthreads();
    }
#pragma unroll
    for (int i = 0; i < 8; i++) {
        int k = trow * 4 + (i & 3) + ((i >> 2) << 6);
        if (k >= K) continue;
#pragma unroll
        for (int jg = 0; jg < 2; jg++) {
            int b = bn + tcol * 4 + (jg << 6);
            float4 o = {acc[i][jg * 4 + 0], acc[i][jg * 4 + 1],
                        acc[i][jg * 4 + 2], acc[i][jg * 4 + 3]};
            *(float4*)&part[((long)z * K + k) * BSZ + b] = o;
        }
    }
}

// reduce split-K partials and multiply by theta: xcur = theta * sum_z part[z]
__global__ void reduce_xmul_kernel(int K, int Z,
                                   const float* __restrict__ part,
                                   const float* __restrict__ theta,
                                   float* __restrict__ xcur) {
    int idx = blockIdx.x * 256 + threadIdx.x;
    int n = K * BSZ;
    if (idx < n) {
        float s = 0.f;
        for (int z = 0; z < Z; z++) s += part[z * n + idx];
        xcur[idx] = theta[idx] * s;
    }
}

// fused TLASGR step + simplex shift: W <- p = max(EPS, step - (T-1)*phi); P += colsum(p)
// T computed analytically from S, phisum, qsum.
__global__ void step_p_kernel(int D, int K,
                              float* __restrict__ W,
                              const float* __restrict__ phi,
                              const float* __restrict__ noise,
                              const float* __restrict__ S,
                              const float* __restrict__ phisum,
                              const float* __restrict__ qsum,
                              float* __restrict__ P) {
    __shared__ float sP[128];
    int tid = threadIdx.x;
    if (tid < K) sP[tid] = 0.f;
    __syncthreads();
    int base = blockIdx.x * 4096;
    int k = (base + tid) & (K - 1);
    float s = S[k];
    float inv_n = 1.f / fmaxf(MBR * s, EPSF);
    float tmpsum = MBR * s + 0.1f * (float)D;
    float c2 = sqrtf(2.f * inv_n);
    float psum = phisum[k];
    float T = psum + inv_n * (tmpsum - tmpsum * psum) + c2 * qsum[k];
    float a = T - 1.f;
    float acc = 0.f;
    int DK = D * K;
#pragma unroll 4
    for (int e = 0; e < 16; e++) {
        int idx = base + e * 256 + tid;
        if (idx < DK) {
            float w = W[idx], ph = phi[idx], nz = noise[idx];
            float st = ph + inv_n * (MBR * w + 0.1f - tmpsum * ph) + c2 * sqrtf(ph) * nz;
            float p = fmaxf(EPSF, st - a * ph);
            W[idx] = p;
            acc += p;
        }
    }
    atomicAdd(&sP[k], acc);
    __syncthreads();
    if (tid < K) atomicAdd(&P[tid], sP[tid]);
}

// normalize: out = p / max(EPS, P[k])
__global__ void norm_kernel(int DK, int K,
                            const float* __restrict__ W,
                            const float* __restrict__ P,
                            float* __restrict__ out) {
    int base = blockIdx.x * 2048;
    int tid = threadIdx.x;
    int k = (base + tid) & (K - 1);
    float inv = 1.f / fmaxf(EPSF, P[k]);
#pragma unroll
    for (int e = 0; e < 8; e++) {
        int idx = base + e * 256 + tid;
        if (idx < DK) out[idx] = W[idx] * inv;
    }
}

// ---------------- host orchestration ----------------
static void run_layer(int t, int D, int K,
                      const float* phi, const float* theta, const float* noise,
                      const float* xin, float* ratio, float* W, float* part,
                      float* xout, float* S, float* P, float* phisum, float* qsum,
                      float* out, int Z) {
    zero4_kernel<<<1, 128>>>(S, P, phisum, qsum, K);
    int nblk = (D * K + 4095) / 4096;
    colstats_kernel<<<nblk, 256>>>(D, K, phi, noise, phisum, qsum);

    dim3 g1(BSZ / 128, (D + 127) / 128);
    ratio_gemm_opt<<<g1, 256>>>(D, K, phi, theta, xin, (t == 0) ? 0 : 1, ratio);

    dim3 g2((K + 127) / 128, (D + 127) / 128);
    wszs_gemm_opt<<<g2, 256>>>(D, K, ratio, theta, phi, W, S);

    step_p_kernel<<<nblk, 256>>>(D, K, W, phi, noise, S, phisum, qsum, P);
    norm_kernel<<<(D * K + 2047) / 2048, 256>>>(D * K, K, W, P, out);

    if (xout) {
        int chunk = (D + Z - 1) / Z;
        dim3 g3(BSZ / 128, 1, Z);
        xnext_gemm_opt<<<g3, 256>>>(D, K, chunk, phi, ratio, part);
        reduce_xmul_kernel<<<(K * BSZ + 255) / 256, 256>>>(K, Z, part, theta, xout);
    }
}

extern "C" void kernel_launch(void* const* d_in, const int* in_sizes, int n_in,
                              void* d_out, int out_size) {
    const float* x      = (const float*)d_in[0];
    const float* theta0 = (const float*)d_in[1];
    const float* theta1 = (const float*)d_in[2];
    const float* theta2 = (const float*)d_in[3];
    const float* phi0   = (const float*)d_in[4];
    const float* phi1   = (const float*)d_in[5];
    const float* phi2   = (const float*)d_in[6];
    const float* noise0 = (const float*)d_in[7];
    const float* noise1 = (const float*)d_in[8];
    const float* noise2 = (const float*)d_in[9];
    float* out = (float*)d_out;

    float *xT, *ratio, *W, *part, *xa, *xb, *S, *P, *phisum, *qsum;
    cudaGetSymbolAddress((void**)&xT, g_xT);
    cudaGetSymbolAddress((void**)&ratio, g_ratio);
    cudaGetSymbolAddress((void**)&W, g_W);
    cudaGetSymbolAddress((void**)&part, g_part);
    cudaGetSymbolAddress((void**)&xa, g_xa);
    cudaGetSymbolAddress((void**)&xb, g_xb);
    cudaGetSymbolAddress((void**)&S, g_S);
    cudaGetSymbolAddress((void**)&P, g_P);
    cudaGetSymbolAddress((void**)&phisum, g_phisum);
    cudaGetSymbolAddress((void**)&qsum, g_qsum);

    dim3 gt((VV + 31) / 32, BSZ / 32);
    transpose_kernel<<<gt, dim3(32, 8)>>>(x, xT);

    // Layer 0: D=30000, K=128
    run_layer(0, VV, 128, phi0, theta0, noise0, xT, ratio, W, part, xa,
              S, P, phisum, qsum, out, NZ0);
    // Layer 1: D=128, K=64
    run_layer(1, 128, 64, phi1, theta1, noise1, xa, ratio, W, part, xb,
              S, P, phisum, qsum, out + VV * 128, 1);
    // Layer 2: D=64, K=32
    run_layer(2, 64, 32, phi2, theta2, noise2, xb, ratio, W, part, nullptr,
              S, P, phisum, qsum, out + VV * 128 + 128 * 64, 1);
}

// round 3
// speedup vs baseline: 1.2853x; 1.0593x over previous
#include <cuda_runtime.h>
#include <cstdint>

#define BSZ 512
#define VV  30000
#define K0  128
#define EPSF 2.2e-10f
#define MBR 100.0f
#define NZ0 37          // split-K slices for layer-0 xnext (37*4 = 148 blocks)

// ---------------- scratch (device globals: allocation-free) ----------------
__device__ float g_xT[VV * BSZ];
__device__ float g_ratio[VV * BSZ];
__device__ float g_W[VV * K0];
__device__ float g_part[NZ0 * K0 * BSZ];
__device__ float g_xa[K0 * BSZ];
__device__ float g_xb[K0 * BSZ];
__device__ float g_S[K0];
__device__ float g_P[K0];
__device__ float g_phisum[K0];
__device__ float g_qsum[K0];

// ---------------- digamma ----------------
__device__ __forceinline__ float digammaf_(float x) {
    float r = 0.f;
    while (x < 6.f) { r -= 1.f / x; x += 1.f; }
    float inv  = 1.f / x;
    float inv2 = inv * inv;
    float ser  = inv2 * (0.08333333333f - inv2 * (0.008333333333f - inv2 * 0.003968253968f));
    return r + logf(x) - 0.5f * inv - ser;
}

// ---------------- tf32 helpers ----------------
__device__ __forceinline__ void split_tf32(float x, uint32_t& hi, uint32_t& lo) {
    asm("cvt.rna.tf32.f32 %0, %1;" : "=r"(hi) : "f"(x));
    float r = x - __uint_as_float(hi);
    asm("cvt.rna.tf32.f32 %0, %1;" : "=r"(lo) : "f"(r));
}

__device__ __forceinline__ void mma8(float* d,
                                     uint32_t a0, uint32_t a1, uint32_t a2, uint32_t a3,
                                     uint32_t b0, uint32_t b1) {
    asm volatile(
        "mma.sync.aligned.m16n8k8.row.col.f32.tf32.tf32.f32 "
        "{%0,%1,%2,%3},{%4,%5,%6,%7},{%8,%9},{%0,%1,%2,%3};\n"
        : "+f"(d[0]), "+f"(d[1]), "+f"(d[2]), "+f"(d[3])
        : "r"(a0), "r"(a1), "r"(a2), "r"(a3), "r"(b0), "r"(b1));
}

// ---------------- zero small accumulators ----------------
__global__ void zero4_kernel(float* S, float* P, float* A, float* Q, int K) {
    int i = threadIdx.x;
    if (i < K) { S[i] = 0.f; P[i] = 0.f; A[i] = 0.f; Q[i] = 0.f; }
}

// ---------------- transpose x (B,V) -> (V,B) ----------------
__global__ void transpose_kernel(const float* __restrict__ x, float* __restrict__ xT) {
    __shared__ float tile[32][33];
    int v0 = blockIdx.x * 32, b0 = blockIdx.y * 32;
    int tx = threadIdx.x, ty = threadIdx.y;
#pragma unroll
    for (int i = 0; i < 32; i += 8) {
        int b = b0 + ty + i, v = v0 + tx;
        tile[ty + i][tx] = (v < VV) ? x[b * VV + v] : 0.f;
    }
    __syncthreads();
#pragma unroll
    for (int i = 0; i < 32; i += 8) {
        int v = v0 + ty + i, b = b0 + tx;
        if (v < VV) xT[v * BSZ + b] = tile[tx][ty + i];
    }
}

// ---------------- colstats ----------------
__global__ void colstats_kernel(int D, int K,
                                const float* __restrict__ phi,
                                const float* __restrict__ noise,
                                float* __restrict__ phisum, float* __restrict__ qsum) {
    __shared__ float sA[128], sB[128];
    int tid = threadIdx.x;
    if (tid < K) { sA[tid] = 0.f; sB[tid] = 0.f; }
    __syncthreads();
    int base = blockIdx.x * 4096;
    int k = (base + tid) & (K - 1);
    float pa = 0.f, pb = 0.f;
    int DK = D * K;
#pragma unroll 4
    for (int e = 0; e < 16; e++) {
        int idx = base + e * 256 + tid;
        if (idx < DK) {
            float ph = phi[idx], nz = noise[idx];
            pa += ph;
            pb += sqrtf(ph) * nz;
        }
    }
    atomicAdd(&sA[k], pa);
    atomicAdd(&sB[k], pb);
    __syncthreads();
    if (tid < K) { atomicAdd(&phisum[tid], sA[tid]); atomicAdd(&qsum[tid], sB[tid]); }
}

// ============================================================================
// Layer-0 tensor-core GEMMs (tf32 split-2). 128x128x32 tiles, 8 warps,
// warp tile 32x64 (wm=wid>>1, wn=wid&1), mma m16n8k8.
// ============================================================================

// GEMM1-TC: denom = phi@theta; ratio = x/denom   (D=VV, K=128, N=512)
__global__ __launch_bounds__(256, 2) void ratio_gemm_tc(
    const float* __restrict__ phi, const float* __restrict__ theta,
    const float* __restrict__ xT, float* __restrict__ ratio) {
    __shared__ float As[32][133];   // [k][v]
    __shared__ float Bs[32][132];   // [k][b]
    const int bn = blockIdx.x * 128;
    const int bv = blockIdx.y * 128;
    const int tid = threadIdx.x;
    const int wid = tid >> 5, lane = tid & 31;
    const int wm = wid >> 1, wn = wid & 1;
    const int g = lane >> 2, c = lane & 3;
    float acc[2][8][4] = {};

    for (int kk = 0; kk < 128; kk += 32) {
#pragma unroll
        for (int e = 0; e < 4; e++) {
            int idx = tid + e * 256;
            int m = idx >> 3, c4 = idx & 7;
            float4 val = make_float4(0.f, 0.f, 0.f, 0.f);
            if (bv + m < VV) val = *(const float4*)&phi[(bv + m) * 128 + kk + c4 * 4];
            As[c4 * 4 + 0][m] = val.x; As[c4 * 4 + 1][m] = val.y;
            As[c4 * 4 + 2][m] = val.z; As[c4 * 4 + 3][m] = val.w;
        }
#pragma unroll
        for (int e = 0; e < 4; e++) {
            int idx = tid + e * 256;
            int r = idx >> 5, c4 = idx & 31;
            *(float4*)&Bs[r][c4 * 4] = *(const float4*)&theta[(kk + r) * BSZ + bn + c4 * 4];
        }
        __syncthreads();
#pragma unroll
        for (int k8 = 0; k8 < 4; k8++) {
            int k0 = k8 * 8;
            uint32_t ahi[2][4], alo[2][4];
#pragma unroll
            for (int mt = 0; mt < 2; mt++) {
                int r = wm * 32 + mt * 16 + g;
                split_tf32(As[k0 + c][r],         ahi[mt][0], alo[mt][0]);
                split_tf32(As[k0 + c][r + 8],     ahi[mt][1], alo[mt][1]);
                split_tf32(As[k0 + c + 4][r],     ahi[mt][2], alo[mt][2]);
                split_tf32(As[k0 + c + 4][r + 8], ahi[mt][3], alo[mt][3]);
            }
#pragma unroll
            for (int nt = 0; nt < 8; nt++) {
                int n = wn * 64 + nt * 8 + g;
                uint32_t bh0, bl0, bh1, bl1;
                split_tf32(Bs[k0 + c][n],     bh0, bl0);
                split_tf32(Bs[k0 + c + 4][n], bh1, bl1);
#pragma unroll
                for (int mt = 0; mt < 2; mt++) {
                    float* d = acc[mt][nt];
                    mma8(d, ahi[mt][0], ahi[mt][1], ahi[mt][2], ahi[mt][3], bh0, bh1);
                    mma8(d, ahi[mt][0], ahi[mt][1], ahi[mt][2], ahi[mt][3], bl0, bl1);
                    mma8(d, alo[mt][0], alo[mt][1], alo[mt][2], alo[mt][3], bh0, bh1);
                }
            }
        }
        __syncthreads();
    }
#pragma unroll
    for (int mt = 0; mt < 2; mt++)
#pragma unroll
        for (int half = 0; half < 2; half++) {
            int v = bv + wm * 32 + mt * 16 + g + half * 8;
            if (v >= VV) continue;
#pragma unroll
            for (int nt = 0; nt < 8; nt++) {
                int b = bn + wn * 64 + nt * 8 + c * 2;
                float2 xv = *(const float2*)&xT[v * BSZ + b];
                float d0 = fmaxf(acc[mt][nt][half * 2 + 0], EPSF);
                float d1 = fmaxf(acc[mt][nt][half * 2 + 1], EPSF);
                float2 o = {xv.x / d0, xv.y / d1};
                *(float2*)&ratio[v * BSZ + b] = o;
            }
        }
}

// GEMM2-TC: W[v][k] = phi[v][k] * sum_b ratio[v][b]*theta[k][b]; S colsum (D=VV, N=K0=128, Kred=512)
__global__ __launch_bounds__(256, 2) void wszs_gemm_tc(
    const float* __restrict__ ratio, const float* __restrict__ theta,
    const float* __restrict__ phi, float* __restrict__ W, float* __restrict__ S) {
    __shared__ float As[32][133];   // [b][v]
    __shared__ float Bs[32][133];   // [b][k]
    __shared__ float sS[128];
    const int bv = blockIdx.y * 128;
    const int tid = threadIdx.x;
    const int wid = tid >> 5, lane = tid & 31;
    const int wm = wid >> 1, wn = wid & 1;
    const int g = lane >> 2, c = lane & 3;
    float acc[2][8][4] = {};

    for (int kk = 0; kk < BSZ; kk += 32) {
#pragma unroll
        for (int e = 0; e < 4; e++) {
            int idx = tid + e * 256;
            int m = idx >> 3, c4 = idx & 7;
            float4 val = make_float4(0.f, 0.f, 0.f, 0.f);
            if (bv + m < VV) val = *(const float4*)&ratio[(bv + m) * BSZ + kk + c4 * 4];
            As[c4 * 4 + 0][m] = val.x; As[c4 * 4 + 1][m] = val.y;
            As[c4 * 4 + 2][m] = val.z; As[c4 * 4 + 3][m] = val.w;
        }
#pragma unroll
        for (int e = 0; e < 4; e++) {
            int idx = tid + e * 256;
            int kcol = idx >> 3, c4 = idx & 7;
            float4 val = *(const float4*)&theta[kcol * BSZ + kk + c4 * 4];
            Bs[c4 * 4 + 0][kcol] = val.x; Bs[c4 * 4 + 1][kcol] = val.y;
            Bs[c4 * 4 + 2][kcol] = val.z; Bs[c4 * 4 + 3][kcol] = val.w;
        }
        __syncthreads();
#pragma unroll
        for (int k8 = 0; k8 < 4; k8++) {
            int k0 = k8 * 8;
            uint32_t ahi[2][4], alo[2][4];
#pragma unroll
            for (int mt = 0; mt < 2; mt++) {
                int r = wm * 32 + mt * 16 + g;
                split_tf32(As[k0 + c][r],         ahi[mt][0], alo[mt][0]);
                split_tf32(As[k0 + c][r + 8],     ahi[mt][1], alo[mt][1]);
                split_tf32(As[k0 + c + 4][r],     ahi[mt][2], alo[mt][2]);
                split_tf32(As[k0 + c + 4][r + 8], ahi[mt][3], alo[mt][3]);
            }
#pragma unroll
            for (int nt = 0; nt < 8; nt++) {
                int n = wn * 64 + nt * 8 + g;
                uint32_t bh0, bl0, bh1, bl1;
                split_tf32(Bs[k0 + c][n],     bh0, bl0);
                split_tf32(Bs[k0 + c + 4][n], bh1, bl1);
#pragma unroll
                for (int mt = 0; mt < 2; mt++) {
                    float* d = acc[mt][nt];
                    mma8(d, ahi[mt][0], ahi[mt][1], ahi[mt][2], ahi[mt][3], bh0, bh1);
                    mma8(d, ahi[mt][0], ahi[mt][1], ahi[mt][2], ahi[mt][3], bl0, bl1);
                    mma8(d, alo[mt][0], alo[mt][1], alo[mt][2], alo[mt][3], bh0, bh1);
                }
            }
        }
        __syncthreads();
    }
    if (tid < 128) sS[tid] = 0.f;
    __syncthreads();
    float colp[8][2] = {};
#pragma unroll
    for (int mt = 0; mt < 2; mt++)
#pragma unroll
        for (int half = 0; half < 2; half++) {
            int v = bv + wm * 32 + mt * 16 + g + half * 8;
            if (v >= VV) continue;
#pragma unroll
            for (int nt = 0; nt < 8; nt++) {
                int k = wn * 64 + nt * 8 + c * 2;
                float2 ph = *(const float2*)&phi[v * 128 + k];
                float w0 = ph.x * acc[mt][nt][half * 2 + 0];
                float w1 = ph.y * acc[mt][nt][half * 2 + 1];
                float2 o = {w0, w1};
                *(float2*)&W[v * 128 + k] = o;
                colp[nt][0] += w0;
                colp[nt][1] += w1;
            }
        }
#pragma unroll
    for (int nt = 0; nt < 8; nt++) {
        int k = wn * 64 + nt * 8 + c * 2;
        atomicAdd(&sS[k], colp[nt][0]);
        atomicAdd(&sS[k + 1], colp[nt][1]);
    }
    __syncthreads();
    if (tid < 128) atomicAdd(&S[tid], sS[tid]);
}

// GEMM3-TC (split-K over v): part[z][k][b] = sum_{v in chunk} phi[v][k]*ratio[v][b]
__global__ __launch_bounds__(256, 2) void xnext_gemm_tc(
    int chunk,
    const float* __restrict__ phi, const float* __restrict__ ratio,
    float* __restrict__ part) {
    __shared__ float As[32][132];   // [v][k]
    __shared__ float Bs[32][132];   // [v][b]
    const int bn = blockIdx.x * 128;
    const int z = blockIdx.z;
    const int v0 = z * chunk;
    const int vend = min(v0 + chunk, VV);
    const int tid = threadIdx.x;
    const int wid = tid >> 5, lane = tid & 31;
    const int wm = wid >> 1, wn = wid & 1;
    const int g = lane >> 2, c = lane & 3;
    float acc[2][8][4] = {};

    for (int vv = v0; vv < vend; vv += 32) {
#pragma unroll
        for (int e = 0; e < 4; e++) {
            int idx = tid + e * 256;
            int vi = idx >> 5, c4 = idx & 31;
            float4 val = make_float4(0.f, 0.f, 0.f, 0.f);
            if (vv + vi < vend) val = *(const float4*)&phi[(vv + vi) * 128 + c4 * 4];
            *(float4*)&As[vi][c4 * 4] = val;
        }
#pragma unroll
        for (int e = 0; e < 4; e++) {
            int idx = tid + e * 256;
            int vi = idx >> 5, c4 = idx & 31;
            float4 val = make_float4(0.f, 0.f, 0.f, 0.f);
            if (vv + vi < vend) val = *(const float4*)&ratio[(vv + vi) * BSZ + bn + c4 * 4];
            *(float4*)&Bs[vi][c4 * 4] = val;
        }
        __syncthreads();
#pragma unroll
        for (int k8 = 0; k8 < 4; k8++) {
            int k0 = k8 * 8;
            uint32_t ahi[2][4], alo[2][4];
#pragma unroll
            for (int mt = 0; mt < 2; mt++) {
                int r = wm * 32 + mt * 16 + g;
                split_tf32(As[k0 + c][r],         ahi[mt][0], alo[mt][0]);
                split_tf32(As[k0 + c][r + 8],     ahi[mt][1], alo[mt][1]);
                split_tf32(As[k0 + c + 4][r],     ahi[mt][2], alo[mt][2]);
                split_tf32(As[k0 + c + 4][r + 8], ahi[mt][3], alo[mt][3]);
            }
#pragma unroll
            for (int nt = 0; nt < 8; nt++) {
                int n = wn * 64 + nt * 8 + g;
                uint32_t bh0, bl0, bh1, bl1;
                split_tf32(Bs[k0 + c][n],     bh0, bl0);
                split_tf32(Bs[k0 + c + 4][n], bh1, bl1);
#pragma unroll
                for (int mt = 0; mt < 2; mt++) {
                    float* d = acc[mt][nt];
                    mma8(d, ahi[mt][0], ahi[mt][1], ahi[mt][2], ahi[mt][3], bh0, bh1);
                    mma8(d, ahi[mt][0], ahi[mt][1], ahi[mt][2], ahi[mt][3], bl0, bl1);
                    mma8(d, alo[mt][0], alo[mt][1], alo[mt][2], alo[mt][3], bh0, bh1);
                }
            }
        }
        __syncthreads();
    }
#pragma unroll
    for (int mt = 0; mt < 2; mt++)
#pragma unroll
        for (int half = 0; half < 2; half++) {
            int k = wm * 32 + mt * 16 + g + half * 8;
#pragma unroll
            for (int nt = 0; nt < 8; nt++) {
                int b = bn + wn * 64 + nt * 8 + c * 2;
                float2 o = {acc[mt][nt][half * 2 + 0], acc[mt][nt][half * 2 + 1]};
                *(float2*)&part[((long)z * 128 + k) * BSZ + b] = o;
            }
        }
}

// ============================================================================
// Generic SIMT kernels (layers 1-2, small dims)
// ============================================================================

__global__ __launch_bounds__(256, 2) void ratio_gemm_opt(
    int D, int K,
    const float* __restrict__ phi, const float* __restrict__ theta,
    const float* __restrict__ xcur, int mode, float* __restrict__ ratio) {
    __shared__ float As[16][132];
    __shared__ float Bs[16][132];
    const int bn = blockIdx.x * 128;
    const int bv = blockIdx.y * 128;
    const int tid = threadIdx.x;
    const int trow = tid >> 4, tcol = tid & 15;
    float acc[8][8] = {};

    for (int kk = 0; kk < K; kk += 16) {
#pragma unroll
        for (int e = 0; e < 8; e++) {
            int idx = tid + e * 256;
            int ic = idx & 15, m = idx >> 4;
            As[ic][m] = (bv + m < D) ? phi[(bv + m) * K + kk + ic] : 0.f;
        }
#pragma unroll
        for (int e = 0; e < 2; e++) {
            int idx = tid + e * 256;
            int r = idx >> 5, c4 = idx & 31;
            *(float4*)&Bs[r][c4 * 4] = *(const float4*)&theta[(kk + r) * BSZ + bn + c4 * 4];
        }
        __syncthreads();
#pragma unroll
        for (int kc = 0; kc < 16; kc++) {
            float a[8], b[8];
            *(float4*)&a[0] = *(float4*)&As[kc][trow * 4];
            *(float4*)&a[4] = *(float4*)&As[kc][trow * 4 + 64];
            *(float4*)&b[0] = *(float4*)&Bs[kc][tcol * 4];
            *(float4*)&b[4] = *(float4*)&Bs[kc][tcol * 4 + 64];
#pragma unroll
            for (int i = 0; i < 8; i++)
#pragma unroll
                for (int j = 0; j < 8; j++) acc[i][j] += a[i] * b[j];
        }
        __syncthreads();
    }
#pragma unroll
    for (int i = 0; i < 8; i++) {
        int v = bv + trow * 4 + (i & 3) + ((i >> 2) << 6);
        if (v >= D) continue;
#pragma unroll
        for (int jg = 0; jg < 2; jg++) {
            int b = bn + tcol * 4 + (jg << 6);
            float4 xv = *(const float4*)&xcur[v * BSZ + b];
            float xs[4] = {xv.x, xv.y, xv.z, xv.w};
            float rs[4];
#pragma unroll
            for (int j = 0; j < 4; j++) {
                float d = fmaxf(acc[i][jg * 4 + j], EPSF);
                rs[j] = (mode == 0) ? xs[j] / d
                                    : digammaf_(d + xs[j]) - digammaf_(d);
            }
            float4 r4 = {rs[0], rs[1], rs[2], rs[3]};
            *(float4*)&ratio[v * BSZ + b] = r4;
        }
    }
}

__global__ __launch_bounds__(256, 2) void wszs_gemm_opt(
    int D, int K,
    const float* __restrict__ ratio, const float* __restrict__ theta,
    const float* __restrict__ phi, float* __restrict__ W, float* __restrict__ S) {
    __shared__ float As[16][132];
    __shared__ float Bs[16][132];
    __shared__ float sS[128];
    const int bn = blockIdx.x * 128;
    const int bv = blockIdx.y * 128;
    const int tid = threadIdx.x;
    const int trow = tid >> 4, tcol = tid & 15;
    float acc[8][8] = {};

    for (int kk = 0; kk < BSZ; kk += 16) {
#pragma unroll
        for (int e = 0; e < 8; e++) {
            int idx = tid + e * 256;
            int ic = idx & 15, m = idx >> 4;
            As[ic][m] = (bv + m < D) ? ratio[(bv + m) * BSZ + kk + ic] : 0.f;
        }
#pragma unroll
        for (int e = 0; e < 8; e++) {
            int idx = tid + e * 256;
            int ic = idx & 15, m = idx >> 4;
            Bs[ic][m] = (bn + m < K) ? theta[(bn + m) * BSZ + kk + ic] : 0.f;
        }
        __syncthreads();
#pragma unroll
        for (int kc = 0; kc < 16; kc++) {
            float a[8], b[8];
            *(float4*)&a[0] = *(float4*)&As[kc][trow * 4];
            *(float4*)&a[4] = *(float4*)&As[kc][trow * 4 + 64];
            *(float4*)&b[0] = *(float4*)&Bs[kc][tcol * 4];
            *(float4*)&b[4] = *(float4*)&Bs[kc][tcol * 4 + 64];
#pragma unroll
            for (int i = 0; i < 8; i++)
#pragma unroll
                for (int j = 0; j < 8; j++) acc[i][j] += a[i] * b[j];
        }
        __syncthreads();
    }
    if (tid < 128) sS[tid] = 0.f;
    __syncthreads();
    float colp[8] = {};
#pragma unroll
    for (int i = 0; i < 8; i++) {
        int v = bv + trow * 4 + (i & 3) + ((i >> 2) << 6);
        if (v >= D) continue;
#pragma unroll
        for (int jg = 0; jg < 2; jg++) {
            int k4 = bn + tcol * 4 + (jg << 6);
            if (k4 < K) {
                float4 ph = *(const float4*)&phi[v * K + k4];
                float4 wv;
                wv.x = ph.x * acc[i][jg * 4 + 0];
                wv.y = ph.y * acc[i][jg * 4 + 1];
                wv.z = ph.z * acc[i][jg * 4 + 2];
                wv.w = ph.w * acc[i][jg * 4 + 3];
                *(float4*)&W[v * K + k4] = wv;
                colp[jg * 4 + 0] += wv.x;
                colp[jg * 4 + 1] += wv.y;
                colp[jg * 4 + 2] += wv.z;
                colp[jg * 4 + 3] += wv.w;
            }
        }
    }
#pragma unroll
    for (int j = 0; j < 8; j++)
        atomicAdd(&sS[tcol * 4 + (j & 3) + ((j >> 2) << 6)], colp[j]);
    __syncthreads();
    if (tid < 128 && bn + tid < K) atomicAdd(&S[bn + tid], sS[tid]);
}

__global__ __launch_bounds__(256, 2) void xnext_gemm_opt(
    int D, int K, int chunk,
    const float* __restrict__ phi, const float* __restrict__ ratio,
    float* __restrict__ part) {
    __shared__ float As[16][132];
    __shared__ float Bs[16][132];
    const int bn = blockIdx.x * 128;
    const int z = blockIdx.z;
    const int v0 = z * chunk;
    const int vend = min(v0 + chunk, D);
    const int tid = threadIdx.x;
    const int trow = tid >> 4, tcol = tid & 15;
    float acc[8][8] = {};

    for (int kk = v0; kk < vend; kk += 16) {
#pragma unroll
        for (int e = 0; e < 2; e++) {
            int idx = tid + e * 256;
            int r = idx >> 5, c4 = idx & 31;
            float4 val = {0.f, 0.f, 0.f, 0.f};
            if (kk + r < vend && c4 * 4 < K)
                val = *(const float4*)&phi[(kk + r) * K + c4 * 4];
            *(float4*)&As[r][c4 * 4] = val;
        }
#pragma unroll
        for (int e = 0; e < 2; e++) {
            int idx = tid + e * 256;
            int r = idx >> 5, c4 = idx & 31;
            float4 val = {0.f, 0.f, 0.f, 0.f};
            if (kk + r < vend)
                val = *(const float4*)&ratio[(kk + r) * BSZ + bn + c4 * 4];
            *(float4*)&Bs[r][c4 * 4] = val;
        }
        __syncthreads();
#pragma unroll
        for (int kc = 0; kc < 16; kc++) {
            float a[8], b[8];
            *(float4*)&a[0] = *(float4*)&As[kc][trow * 4];
            *(float4*)&a[4] = *(float4*)&As[kc][trow * 4 + 64];
            *(float4*)&b[0] = *(float4*)&Bs[kc][tcol * 4];
            *(float4*)&b[4] = *(float4*)&Bs[kc][tcol * 4 + 64];
#pragma unroll
            for (int i = 0; i < 8; i++)
#pragma unroll
                for (int j = 0; j < 8; j++) acc[i][j] += a[i] * b[j];
        }
        __syncthreads();
    }
#pragma unroll
    for (int i = 0; i < 8; i++) {
        int k = trow * 4 + (i & 3) + ((i >> 2) << 6);
        if (k >= K) continue;
#pragma unroll
        for (int jg = 0; jg < 2; jg++) {
            int b = bn + tcol * 4 + (jg << 6);
            float4 o = {acc[i][jg * 4 + 0], acc[i][jg * 4 + 1],
                        acc[i][jg * 4 + 2], acc[i][jg * 4 + 3]};
            *(float4*)&part[((long)z * K + k) * BSZ + b] = o;
        }
    }
}

// ---------------- common epilogue kernels ----------------
__global__ void reduce_xmul_kernel(int K, int Z,
                                   const float* __restrict__ part,
                                   const float* __restrict__ theta,
                                   float* __restrict__ xcur) {
    int idx = blockIdx.x * 256 + threadIdx.x;
    int n = K * BSZ;
    if (idx < n) {
        float s = 0.f;
        for (int z = 0; z < Z; z++) s += part[z * n + idx];
        xcur[idx] = theta[idx] * s;
    }
}

__global__ void step_p_kernel(int D, int K,
                              float* __restrict__ W,
                              const float* __restrict__ phi,
                              const float* __restrict__ noise,
                              const float* __restrict__ S,
                              const float* __restrict__ phisum,
                              const float* __restrict__ qsum,
                              float* __restrict__ P) {
    __shared__ float sP[128];
    int tid = threadIdx.x;
    if (tid < K) sP[tid] = 0.f;
    __syncthreads();
    int base = blockIdx.x * 4096;
    int k = (base + tid) & (K - 1);
    float s = S[k];
    float inv_n = 1.f / fmaxf(MBR * s, EPSF);
    float tmpsum = MBR * s + 0.1f * (float)D;
    float c2 = sqrtf(2.f * inv_n);
    float psum = phisum[k];
    float T = psum + inv_n * (tmpsum - tmpsum * psum) + c2 * qsum[k];
    float a = T - 1.f;
    float acc = 0.f;
    int DK = D * K;
#pragma unroll 4
    for (int e = 0; e < 16; e++) {
        int idx = base + e * 256 + tid;
        if (idx < DK) {
            float w = W[idx], ph = phi[idx], nz = noise[idx];
            float st = ph + inv_n * (MBR * w + 0.1f - tmpsum * ph) + c2 * sqrtf(ph) * nz;
            float p = fmaxf(EPSF, st - a * ph);
            W[idx] = p;
            acc += p;
        }
    }
    atomicAdd(&sP[k], acc);
    __syncthreads();
    if (tid < K) atomicAdd(&P[tid], sP[tid]);
}

__global__ void norm_kernel(int DK, int K,
                            const float* __restrict__ W,
                            const float* __restrict__ P,
                            float* __restrict__ out) {
    int base = blockIdx.x * 2048;
    int tid = threadIdx.x;
    int k = (base + tid) & (K - 1);
    float inv = 1.f / fmaxf(EPSF, P[k]);
#pragma unroll
    for (int e = 0; e < 8; e++) {
        int idx = base + e * 256 + tid;
        if (idx < DK) out[idx] = W[idx] * inv;
    }
}

// ---------------- host orchestration ----------------
static void run_layer_small(int t, int D, int K,
                            const float* phi, const float* theta, const float* noise,
                            const float* xin, float* ratio, float* W, float* part,
                            float* xout, float* S, float* P, float* phisum, float* qsum,
                            float* out) {
    zero4_kernel<<<1, 128>>>(S, P, phisum, qsum, K);
    int nblk = (D * K + 4095) / 4096;
    colstats_kernel<<<nblk, 256>>>(D, K, phi, noise, phisum, qsum);

    dim3 g1(BSZ / 128, (D + 127) / 128);
    ratio_gemm_opt<<<g1, 256>>>(D, K, phi, theta, xin, 1, ratio);

    dim3 g2((K + 127) / 128, (D + 127) / 128);
    wszs_gemm_opt<<<g2, 256>>>(D, K, ratio, theta, phi, W, S);

    step_p_kernel<<<nblk, 256>>>(D, K, W, phi, noise, S, phisum, qsum, P);
    norm_kernel<<<(D * K + 2047) / 2048, 256>>>(D * K, K, W, P, out);

    if (xout) {
        dim3 g3(BSZ / 128, 1, 1);
        xnext_gemm_opt<<<g3, 256>>>(D, K, D, phi, ratio, part);
        reduce_xmul_kernel<<<(K * BSZ + 255) / 256, 256>>>(K, 1, part, theta, xout);
    }
}

extern "C" void kernel_launch(void* const* d_in, const int* in_sizes, int n_in,
                              void* d_out, int out_size) {
    const float* x      = (const float*)d_in[0];
    const float* theta0 = (const float*)d_in[1];
    const float* theta1 = (const float*)d_in[2];
    const float* theta2 = (const float*)d_in[3];
    const float* phi0   = (const float*)d_in[4];
    const float* phi1   = (const float*)d_in[5];
    const float* phi2   = (const float*)d_in[6];
    const float* noise0 = (const float*)d_in[7];
    const float* noise1 = (const float*)d_in[8];
    const float* noise2 = (const float*)d_in[9];
    float* out = (float*)d_out;

    float *xT, *ratio, *W, *part, *xa, *xb, *S, *P, *phisum, *qsum;
    cudaGetSymbolAddress((void**)&xT, g_xT);
    cudaGetSymbolAddress((void**)&ratio, g_ratio);
    cudaGetSymbolAddress((void**)&W, g_W);
    cudaGetSymbolAddress((void**)&part, g_part);
    cudaGetSymbolAddress((void**)&xa, g_xa);
    cudaGetSymbolAddress((void**)&xb, g_xb);
    cudaGetSymbolAddress((void**)&S, g_S);
    cudaGetSymbolAddress((void**)&P, g_P);
    cudaGetSymbolAddress((void**)&phisum, g_phisum);
    cudaGetSymbolAddress((void**)&qsum, g_qsum);

    dim3 gt((VV + 31) / 32, BSZ / 32);
    transpose_kernel<<<gt, dim3(32, 8)>>>(x, xT);

    // ---- Layer 0 (D=30000, K=128): tensor-core path ----
    zero4_kernel<<<1, 128>>>(S, P, phisum, qsum, 128);
    int nblk0 = (VV * 128 + 4095) / 4096;
    colstats_kernel<<<nblk0, 256>>>(VV, 128, phi0, noise0, phisum, qsum);

    dim3 g1(BSZ / 128, (VV + 127) / 128);
    ratio_gemm_tc<<<g1, 256>>>(phi0, theta0, xT, ratio);

    dim3 g2(1, (VV + 127) / 128);
    wszs_gemm_tc<<<g2, 256>>>(ratio, theta0, phi0, W, S);

    step_p_kernel<<<nblk0, 256>>>(VV, 128, W, phi0, noise0, S, phisum, qsum, P);
    norm_kernel<<<(VV * 128 + 2047) / 2048, 256>>>(VV * 128, 128, W, P, out);

    int chunk = (VV + NZ0 - 1) / NZ0;
    dim3 g3(BSZ / 128, 1, NZ0);
    xnext_gemm_tc<<<g3, 256>>>(chunk, phi0, ratio, part);
    reduce_xmul_kernel<<<(128 * BSZ + 255) / 256, 256>>>(128, NZ0, part, theta0, xa);

    // ---- Layers 1-2: SIMT path ----
    run_layer_small(1, 128, 64, phi1, theta1, noise1, xa, ratio, W, part, xb,
                    S, P, phisum, qsum, out + VV * 128);
    run_layer_small(2, 64, 32, phi2, theta2, noise2, xb, ratio, W, part, nullptr,
                    S, P, phisum, qsum, out + VV * 128 + 128 * 64);
}